// round 5
// baseline (speedup 1.0000x reference)
#include <cuda_runtime.h>

// Pair_83811991814342: out[i*512+j] = concat(x[i], x[j], inter/area_i, inter/area_j)
// n = 512, d = 260, out rows of 522 floats. HBM-store-bound (~547 MB writes,
// sustained 6.18 TB/s at 88.5us -> 77% of spec; targeting ~85%).
//
// R4 = R3 resubmitted (R3 bench was an infra failure, not a kernel result):
// TI=8 x TJ=16 tile (smem 38.5->26 KB), warp-per-i with 16 contiguous
// j-rows, running-pointer + immediate-offset stores, launch_bounds(256,5)
// to lift occupancy 45% -> ~60%.

#define DD      260
#define TI      8
#define TJ      16
#define NTHREADS 256

__global__ __launch_bounds__(NTHREADS, 5)
void pair_kernel(const float* __restrict__ in, float* __restrict__ out, int n)
{
    __shared__ float  xi[TI][DD];
    __shared__ float  xj[TJ][DD];
    __shared__ float2 r12[TI][TJ];

    const int tid = threadIdx.x;
    const int i0  = blockIdx.y * TI;
    const int j0  = blockIdx.x * TJ;

    // ---- Phase 1: cooperative float4 copy of tiles into SMEM ----
    {
        const float4* gi = (const float4*)(in + (size_t)i0 * DD);   // 16B aligned: 260*4*i0 % 16 == 0
        float4*       si = (float4*)&xi[0][0];
        #pragma unroll
        for (int t = tid; t < TI * DD / 4; t += NTHREADS) si[t] = gi[t];

        const float4* gj = (const float4*)(in + (size_t)j0 * DD);
        float4*       sj = (float4*)&xj[0][0];
        #pragma unroll
        for (int t = tid; t < TJ * DD / 4; t += NTHREADS) sj[t] = gj[t];
    }
    __syncthreads();

    // ---- Phase 2: precompute (r1, r2) for all TI x TJ pairs ----
    if (tid < TI * TJ) {
        const int ii = tid / TJ;
        const int jj = tid % TJ;
        const float x1i = xi[ii][256], y1i = xi[ii][257];
        const float x2i = xi[ii][258], y2i = xi[ii][259];
        const float x1j = xj[jj][256], y1j = xj[jj][257];
        const float x2j = xj[jj][258], y2j = xj[jj][259];
        const float ai = (x2i - x1i) * (y2i - y1i);
        const float aj = (x2j - x1j) * (y2j - y1j);
        const float w  = fmaxf(0.0f, fminf(x2i, x2j) - fmaxf(x1i, x1j));
        const float h  = fmaxf(0.0f, fminf(y2i, y2j) - fmaxf(y1i, y1j));
        const float inter = w * h;
        r12[ii][jj] = make_float2(inter / ai, inter / aj);
    }
    __syncthreads();

    // ---- Phase 3: one warp per i-row, 16 contiguous j-rows (33 KB stream) ----
    const int wrp  = tid >> 5;        // = il, 0..7
    const int lane = tid & 31;
    const int il   = wrp;

    // Hoist the x[i] half of each row into registers (constant across j).
    const float2* xi2 = (const float2*)&xi[il][0];
    const float2 v0 = xi2[lane];
    const float2 v1 = xi2[lane + 32];
    const float2 v2 = xi2[lane + 64];
    const float2 v3 = xi2[lane + 96];
    // float2 index c = lane+128; c<130 (lane<2) is still x[i].
    const float2 v4 = xi2[(lane < 2) ? (lane + 128) : 128];

    // Rows (i0+il, j0..j0+15) are contiguous in the output: stride 261 float2.
    float2*       o   = (float2*)out + ((size_t)(i0 + il) * (size_t)n + (size_t)j0) * 261;
    const float2* xj2 = (const float2*)&xj[0][0];   // advance 130 per row
    const float2* rr  = &r12[il][0];

    #pragma unroll
    for (int jj = 0; jj < TJ; ++jj) {
        // c = lane + 32*m ; c<130 -> x[i], c<260 -> x[j], c==260 -> (r1,r2)
        o[lane      ] = v0;
        o[lane +  32] = v1;
        o[lane +  64] = v2;
        o[lane +  96] = v3;
        {
            const float2 a = xj2[(lane < 2) ? 0 : (lane - 2)];
            o[lane + 128] = (lane < 2) ? v4 : a;            // c = 128..159
        }
        o[lane + 160] = xj2[lane + 30];                     // c = 160..191
        o[lane + 192] = xj2[lane + 62];                     // c = 192..223
        o[lane + 224] = xj2[lane + 94];                     // c = 224..255
        if (lane < 5) {                                     // c = 256..260
            const float2 tail = (lane < 4) ? xj2[lane + 126] : rr[jj];
            o[lane + 256] = tail;
        }
        o   += 261;
        xj2 += 130;
    }
}

extern "C" void kernel_launch(void* const* d_in, const int* in_sizes, int n_in,
                              void* d_out, int out_size)
{
    const float* in  = (const float*)d_in[0];
    float*       out = (float*)d_out;

    // inputs: (1, 2n, D) fp32 ; n = 512 for this problem
    const int n = (in_sizes[0] / DD) / 2;

    dim3 grid(n / TJ, n / TI);   // (32, 64) = 2048 blocks
    pair_kernel<<<grid, NTHREADS>>>(in, out, n);
}

// round 6
// speedup vs baseline: 1.3286x; 1.3286x over previous
#include <cuda_runtime.h>

// Pair_83811991814342: out[i*512+j] = concat(x[i], x[j], inter/area_i, inter/area_j)
// n = 512, d = 260, rows of 522 floats. HBM-write-bound (547 MB stores).
//
// R6 = R2 (best, 88.5us) + ONE change: streaming stores (__stcs / STG.CS)
// so the 547 MB write sweep doesn't thrash L2 replacement state.
// R4's lesson: do NOT touch the TI=4 x TJ=32 / 64-reg store structure —
// occupancy is not the binder; per-warp store MLP is.

#define DD      260
#define ROWLEN  522          // 2*D + 2 floats per output row
#define TI      4
#define TJ      32
#define NTHREADS 256

__global__ __launch_bounds__(NTHREADS, 1)
void pair_kernel(const float* __restrict__ in, float* __restrict__ out, int n)
{
    __shared__ float  xi[TI][DD];
    __shared__ float  xj[TJ][DD];
    __shared__ float2 r12[TI][TJ];

    const int tid = threadIdx.x;
    const int i0  = blockIdx.y * TI;
    const int j0  = blockIdx.x * TJ;

    // ---- Phase 1: cooperative float4 copy of tiles into SMEM ----
    {
        const float4* gi = (const float4*)(in + (size_t)i0 * DD);
        float4*       si = (float4*)&xi[0][0];
        #pragma unroll
        for (int t = tid; t < TI * DD / 4; t += NTHREADS) si[t] = gi[t];

        const float4* gj = (const float4*)(in + (size_t)j0 * DD);
        float4*       sj = (float4*)&xj[0][0];
        for (int t = tid; t < TJ * DD / 4; t += NTHREADS) sj[t] = gj[t];
    }
    __syncthreads();

    // ---- Phase 2: precompute (r1, r2) for all TI x TJ pairs ----
    if (tid < TI * TJ) {
        const int ii = tid / TJ;
        const int jj = tid % TJ;
        const float x1i = xi[ii][256], y1i = xi[ii][257];
        const float x2i = xi[ii][258], y2i = xi[ii][259];
        const float x1j = xj[jj][256], y1j = xj[jj][257];
        const float x2j = xj[jj][258], y2j = xj[jj][259];
        const float ai = (x2i - x1i) * (y2i - y1i);
        const float aj = (x2j - x1j) * (y2j - y1j);
        const float w  = fmaxf(0.0f, fminf(x2i, x2j) - fmaxf(x1i, x1j));
        const float h  = fmaxf(0.0f, fminf(y2i, y2j) - fmaxf(y1i, y1j));
        const float inter = w * h;
        r12[ii][jj] = make_float2(inter / ai, inter / aj);
    }
    __syncthreads();

    // ---- Phase 3: warp-per-row streaming stores ----
    const int wrp  = tid >> 5;
    const int lane = tid & 31;
    const int il   = wrp >> 1;        // 0..3  (local i)
    const int jh   = wrp & 1;         // 0/1   (j half: 16 rows each)

    // Hoist the x[i] half of each row into registers (constant across j).
    const float2* xi2 = (const float2*)&xi[il][0];
    const float2 v0 = xi2[lane];
    const float2 v1 = xi2[lane + 32];
    const float2 v2 = xi2[lane + 64];
    const float2 v3 = xi2[lane + 96];
    // m=4 covers float2 index c = lane+128; c<130 (i.e. lane<2) is still x[i].
    const float2 v4 = xi2[(lane < 2) ? (lane + 128) : 128];

    const int jbase = jh * 16;
    #pragma unroll 4
    for (int r = 0; r < 16; ++r) {
        const int jj = jbase + r;
        const size_t rowbase = ((size_t)(i0 + il) * (size_t)n + (size_t)(j0 + jj))
                               * (size_t)ROWLEN;
        float2* o = (float2*)(out + rowbase);          // rowbase even -> 8B aligned
        const float2* xj2 = (const float2*)&xj[jj][0];

        // c = lane + 32*m ; c<130 -> x[i], c<260 -> x[j], c==260 -> (r1,r2)
        __stcs(&o[lane      ], v0);
        __stcs(&o[lane +  32], v1);
        __stcs(&o[lane +  64], v2);
        __stcs(&o[lane +  96], v3);
        {
            const float2 a = xj2[(lane < 2) ? 0 : (lane - 2)];
            __stcs(&o[lane + 128], (lane < 2) ? v4 : a);   // c = 128..159
        }
        __stcs(&o[lane + 160], xj2[lane + 30]);            // c = 160..191
        __stcs(&o[lane + 192], xj2[lane + 62]);            // c = 192..223
        __stcs(&o[lane + 224], xj2[lane + 94]);            // c = 224..255
        if (lane < 5) {                                    // c = 256..260
            const float2 tail = (lane < 4) ? xj2[lane + 126] : r12[il][jj];
            __stcs(&o[lane + 256], tail);
        }
    }
}

extern "C" void kernel_launch(void* const* d_in, const int* in_sizes, int n_in,
                              void* d_out, int out_size)
{
    const float* in  = (const float*)d_in[0];
    float*       out = (float*)d_out;

    // inputs: (1, 2n, D) fp32 ; n = 512 for this problem
    const int n = (in_sizes[0] / DD) / 2;

    dim3 grid(n / TJ, n / TI);   // (16, 128) = 2048 blocks
    pair_kernel<<<grid, NTHREADS>>>(in, out, n);
}

// round 8
// speedup vs baseline: 1.3296x; 1.0007x over previous
#include <cuda_runtime.h>

// Pair_83811991814342: out[i*512+j] = concat(x[i], x[j], inter/area_i, inter/area_j)
// n = 512, d = 260, rows of 522 floats. HBM-write-bound (547 MB stores).
//
// R7 = R6 (86.1us) + ONE lever: reg-combined STG.128 stores. Rows are 2088 B,
// alignment alternates with j parity; even rows store 130 aligned float4 + a
// float2 tail, odd rows a leading float2 + 130 aligned float4 (sources
// straddling xi/xj/r12 are assembled from float2 pairs). Cuts L1tex store
// wavefronts ~27 -> ~19 per row. Tile/mapping/.cs unchanged; launch_bounds
// (256,4) pins regs <= 64 so occupancy can't drop below R6's 4 blocks/SM.

#define DD      260
#define ROWLEN  522          // 2*D + 2 floats per output row
#define TI      4
#define TJ      32
#define NTHREADS 256

__global__ __launch_bounds__(NTHREADS, 4)
void pair_kernel(const float* __restrict__ in, float* __restrict__ out, int n)
{
    __shared__ float  xi[TI][DD];
    __shared__ float  xj[TJ][DD];
    __shared__ float2 r12[TI][TJ];

    const int tid = threadIdx.x;
    const int i0  = blockIdx.y * TI;
    const int j0  = blockIdx.x * TJ;

    // ---- Phase 1: cooperative float4 copy of tiles into SMEM ----
    {
        const float4* gi = (const float4*)(in + (size_t)i0 * DD);
        float4*       si = (float4*)&xi[0][0];
        #pragma unroll
        for (int t = tid; t < TI * DD / 4; t += NTHREADS) si[t] = gi[t];

        const float4* gj = (const float4*)(in + (size_t)j0 * DD);
        float4*       sj = (float4*)&xj[0][0];
        for (int t = tid; t < TJ * DD / 4; t += NTHREADS) sj[t] = gj[t];
    }
    __syncthreads();

    // ---- Phase 2: precompute (r1, r2) for all TI x TJ pairs ----
    if (tid < TI * TJ) {
        const int ii = tid / TJ;
        const int jj = tid % TJ;
        const float x1i = xi[ii][256], y1i = xi[ii][257];
        const float x2i = xi[ii][258], y2i = xi[ii][259];
        const float x1j = xj[jj][256], y1j = xj[jj][257];
        const float x2j = xj[jj][258], y2j = xj[jj][259];
        const float ai = (x2i - x1i) * (y2i - y1i);
        const float aj = (x2j - x1j) * (y2j - y1j);
        const float w  = fmaxf(0.0f, fminf(x2i, x2j) - fmaxf(x1i, x1j));
        const float h  = fmaxf(0.0f, fminf(y2i, y2j) - fmaxf(y1i, y1j));
        const float inter = w * h;
        r12[ii][jj] = make_float2(inter / ai, inter / aj);
    }
    __syncthreads();

    // ---- Phase 3: warp-per-row, wide aligned stores ----
    const int wrp  = tid >> 5;
    const int lane = tid & 31;
    const int il   = wrp >> 1;        // 0..3  (local i)
    const int jh   = wrp & 1;         // 0/1   (j half: 16 rows each)

    const float4* xi4 = (const float4*)&xi[il][0];   // il*1040 B, 16B aligned
    const float2* xi2 = (const float2*)&xi[il][0];

    // Row-invariant hoists.
    const float4 w0  = xi4[lane];          // floats 4*lane   .. +3
    const float4 w1  = xi4[lane + 32];     // floats 128+4*lane .. +3
    const float4 x64 = xi4[64];            // floats 256..259 (broadcast)

    const int jbase = jh * 16;
    #pragma unroll 4
    for (int r = 0; r < 16; ++r) {
        const int jj = jbase + r;
        const int j  = j0 + jj;
        const size_t R = ((size_t)(i0 + il) * (size_t)n + (size_t)j) * (size_t)ROWLEN;
        const float2* xj2 = (const float2*)&xj[jj][0];   // jj*1040 B, 16B aligned
        const float4* xj4 = (const float4*)&xj[jj][0];
        const float2  rr  = r12[il][jj];

        if ((j & 1) == 0) {
            // ---- even row: R % 4 == 0, float4-aligned from float 0 ----
            float4* o4 = (float4*)(out + R);
            __stcs(&o4[lane     ], w0);                       // floats 0..127
            __stcs(&o4[lane + 32], w1);                       // floats 128..255
            {   // q = 64 + lane: q==64 -> xi floats 256..259, else xj4[q-65]
                const float4 b = xj4[lane ? (lane - 1) : 0];
                __stcs(&o4[lane + 64], lane ? b : x64);
            }
            __stcs(&o4[lane + 96], xj4[lane + 31]);           // floats 384..511
            if (lane < 2)
                __stcs(&o4[lane + 128], xj4[lane + 63]);      // floats 512..519
            if (lane == 2)
                __stcs((float2*)(out + R) + 260, rr);         // floats 520,521
        } else {
            // ---- odd row: leading float2, then float4-aligned at R+2 ----
            float2* o2 = (float2*)(out + R);
            float4* o4 = (float4*)(out + R + 2);
            if (lane == 0) __stcs(&o2[0], xi2[0]);            // floats 0,1
            {   // q = lane: floats 2+4q -> xi2[1+2q], xi2[2+2q]
                const float2 a0 = xi2[1 + 2*lane], a1 = xi2[2 + 2*lane];
                __stcs(&o4[lane], make_float4(a0.x, a0.y, a1.x, a1.y));
            }
            {   // q = 32+lane
                const float2 b0 = xi2[65 + 2*lane], b1 = xi2[66 + 2*lane];
                __stcs(&o4[lane + 32], make_float4(b0.x, b0.y, b1.x, b1.y));
            }
            {   // q = 64+lane: lane 0 straddles xi->xj
                const float2 c0 = lane ? xj2[2*lane - 1] : xi2[129];
                const float2 c1 = xj2[2*lane];
                __stcs(&o4[lane + 64], make_float4(c0.x, c0.y, c1.x, c1.y));
            }
            {   // q = 96+lane
                const float2 d0 = xj2[63 + 2*lane], d1 = xj2[64 + 2*lane];
                __stcs(&o4[lane + 96], make_float4(d0.x, d0.y, d1.x, d1.y));
            }
            if (lane == 0) {                                  // q = 128
                const float2 e0 = xj2[127], e1 = xj2[128];
                __stcs(&o4[128], make_float4(e0.x, e0.y, e1.x, e1.y));
            }
            if (lane == 1) {                                  // q = 129 (xj tail + r12)
                const float2 f0 = xj2[129];
                __stcs(&o4[129], make_float4(f0.x, f0.y, rr.x, rr.y));
            }
        }
    }
}

extern "C" void kernel_launch(void* const* d_in, const int* in_sizes, int n_in,
                              void* d_out, int out_size)
{
    const float* in  = (const float*)d_in[0];
    float*       out = (float*)d_out;

    // inputs: (1, 2n, D) fp32 ; n = 512 for this problem
    const int n = (in_sizes[0] / DD) / 2;

    dim3 grid(n / TJ, n / TI);   // (16, 128) = 2048 blocks
    pair_kernel<<<grid, NTHREADS>>>(in, out, n);
}